// round 14
// baseline (speedup 1.0000x reference)
#include <cuda_runtime.h>
#include <cstdint>
#include <cstddef>

// ============================================================================
// LSTM (B=8192, H=512, T=32, F=96) on sm_100 via mma.sync.m16n8k8 TF32.
//
// R14 change vs R13 (passed 3862us; step 129.1us, tensor=60.4%, per-SMSP
// issue ~11% => warps stalled ~89%): remove bar.sync lockstep. Per-stage
// mbarriers: full[s] (count 256, fed by cp.async.mbarrier.arrive.noinc per
// thread) and empty[s] (count 8, lane0-per-warp arrive after the chunk's
// MMAs). Warps now wait only on DATA and STAGE-REUSE, not on each other's
// instruction progress -- a warp can run ahead until the 3-deep stage ring
// binds. WAITG/commit_group dropped. Tiling, fragments, k-permutation,
// RAW-ordered MMA issue, epilogue: unchanged from R13 (bit-identical math).
// ============================================================================

#define DEVI __device__ __forceinline__

#define BATCH   8192
#define HID     512
#define G4      2048
#define TSTEPS  32
#define INFEAT  96
#define NCHUNK  19
#define THREADS 256

#define STAGE     32768              // A 16KB | B 16KB
#define SMEM_CTRL (3 * STAGE)        // 98304: 6 mbarriers
#define SMEM_ALLOC (SMEM_CTRL + 256)

#define WT_FLOATS (16 * NCHUNK * 128 * 32)   // 4.75MB pre-tiled W

// ------------------------- device scratch (no allocs) -----------------------
__device__ float g_h[2][BATCH * HID];
__device__ float g_c[BATCH * HID];
__device__ float g_bias[G4];
__device__ float g_Wt[WT_FLOATS];
__device__ float g_xT[TSTEPS * BATCH * INFEAT];

// ------------------------------ helpers -------------------------------------
DEVI uint32_t smem_u32(const void* p) {
    uint32_t a;
    asm("{ .reg .u64 t; cvta.to.shared.u64 t, %1; cvt.u32.u64 %0, t; }" : "=r"(a) : "l"(p));
    return a;
}
DEVI float to_tf32(float x) {
    uint32_t o;
    asm("cvt.rna.tf32.f32 %0, %1;" : "=r"(o) : "f"(x));
    return __uint_as_float(o);
}
DEVI float ex2f(float x) { float y; asm("ex2.approx.f32 %0, %1;" : "=f"(y) : "f"(x)); return y; }
DEVI float rcpf(float x) { float y; asm("rcp.approx.f32 %0, %1;" : "=f"(y) : "f"(x)); return y; }
DEVI float sigm(float x) { return rcpf(1.0f + ex2f(x * -1.44269504088896f)); }
DEVI float tanh_(float x) { return fmaf(2.0f, sigm(x + x), -1.0f); }

DEVI uint32_t swz(uint32_t g) { return ((g & 1u) << 2) | (g >> 1); }

DEVI void cp16(uint32_t sdst, const void* gsrc) {
    asm volatile("cp.async.cg.shared.global [%0], [%1], 16;" :: "r"(sdst), "l"(gsrc) : "memory");
}
DEVI void cp_arrive(uint32_t mbar) {
    asm volatile("cp.async.mbarrier.arrive.noinc.shared::cta.b64 [%0];" :: "r"(mbar) : "memory");
}
DEVI void mma_tf32(float* c, uint32_t a0, uint32_t a1, uint32_t a2, uint32_t a3,
                   uint32_t b0, uint32_t b1) {
    asm volatile(
        "mma.sync.aligned.m16n8k8.row.col.f32.tf32.tf32.f32 "
        "{%0,%1,%2,%3}, {%4,%5,%6,%7}, {%8,%9}, {%0,%1,%2,%3};"
        : "+f"(c[0]), "+f"(c[1]), "+f"(c[2]), "+f"(c[3])
        : "r"(a0), "r"(a1), "r"(a2), "r"(a3), "r"(b0), "r"(b1));
}

#define MBARRIER_INIT(addr, cnt) \
    asm volatile("mbarrier.init.shared.b64 [%0], %1;" :: "r"(addr), "r"((uint32_t)(cnt)) : "memory")
#define MBAR_ARRIVE(addr) \
    asm volatile("mbarrier.arrive.shared.b64 _, [%0];" :: "r"(addr) : "memory")

#define MBARRIER_WAIT_PARITY(addr, par) do {                                        \
    uint32_t _mb = (addr); uint32_t _p = (par); uint32_t _done;                     \
    asm volatile("{\n\t.reg .pred p;\n\t"                                           \
        "mbarrier.try_wait.parity.acquire.cta.shared::cta.b64 p, [%1], %2;\n\t"     \
        "selp.b32 %0, 1, 0, p;\n\t}" : "=r"(_done) : "r"(_mb), "r"(_p) : "memory"); \
    if (!_done) {                                                                   \
        asm volatile("{\n\t.reg .pred P1;\n\t"                                      \
            "WL_%=:\n\t"                                                            \
            "mbarrier.try_wait.parity.acquire.cta.shared::cta.b64 P1, [%0], %1, 0x989680;\n\t" \
            "@P1 bra.uni WD_%=;\n\t"                                                \
            "bra.uni WL_%=;\n\t"                                                    \
            "WD_%=:\n\t}" :: "r"(_mb), "r"(_p) : "memory");                         \
    }                                                                               \
} while (0)

// ------------------------------ prep kernels --------------------------------
__global__ void prep_x_kernel(const float* __restrict__ in) {
    int idx = blockIdx.x * blockDim.x + threadIdx.x;
    if (idx >= BATCH * 3 * 32 * 32) return;
    int w  = idx & 31;
    int t  = (idx >> 5) & 31;
    int c3 = idx >> 10;
    int ch = c3 % 3;
    int b  = c3 / 3;
    g_xT[((size_t)t * BATCH + b) * INFEAT + w * 3 + ch] = to_tf32(in[idx]);
}

__global__ void prep_misc_kernel(const float* __restrict__ h0, const float* __restrict__ c0,
                                 const float* __restrict__ bih, const float* __restrict__ bhh) {
    int i = blockIdx.x * blockDim.x + threadIdx.x;
    if (i < BATCH * HID) {
        g_h[0][i] = to_tf32(h0[i]);
        g_c[i]    = c0[i];
    }
    if (i < G4) g_bias[i] = bih[i] + bhh[i];
}

// g_Wt[(nhi*NCHUNK + kc)*4096 + r*32 + c]: row r = gate(r)*512 + nhi*32 +
// unit(r), swizzle (chunk ^= swz(r&7)) baked in.
__global__ void prep_w_kernel(const float* __restrict__ Wih, const float* __restrict__ Whh) {
    int idx = blockIdx.x * blockDim.x + threadIdx.x;
    if (idx >= WT_FLOATS) return;
    int pos = idx & 4095;
    int kc  = (idx >> 12) % NCHUNK;
    int nhi = idx / (NCHUNK * 4096);
    int r   = pos >> 5;
    int c   = pos & 31;
    int cc_dst = c >> 2, j = c & 3;
    int cc_src = cc_dst ^ (int)swz((uint32_t)(r & 7));
    int k_local = cc_src * 4 + j;
    int wrow = ((r >> 3) & 3) * HID + nhi * 32 + ((r >> 5) << 3) + (r & 7);
    float v;
    if (kc < 16) v = Whh[(size_t)wrow * HID    + kc * 32        + k_local];
    else         v = Wih[(size_t)wrow * INFEAT + (kc - 16) * 32 + k_local];
    g_Wt[idx] = to_tf32(v);
}

// --------------------------- mma compute body --------------------------------
template<int S>
DEVI void mma_chunk(float (&acc)[4][4][4],
                    uint32_t RA0, uint32_t RA1, uint32_t RB0, uint32_t RB1) {
    #pragma unroll
    for (int p = 0; p < 2; p++) {
        const uint32_t RA = (p ? RA1 : RA0) + S * STAGE;
        const uint32_t RB = (p ? RB1 : RB0) + S * STAGE + 16384;
        uint32_t bw[4][4];
        #pragma unroll
        for (int n = 0; n < 4; n++)
            asm volatile("ld.shared.v4.u32 {%0,%1,%2,%3}, [%4];"
                         : "=r"(bw[n][0]), "=r"(bw[n][1]), "=r"(bw[n][2]), "=r"(bw[n][3])
                         : "r"(RB + n * 1024));
        #pragma unroll
        for (int m = 0; m < 4; m++) {
            uint32_t x0, x1, x2, x3, y0, y1, y2, y3;
            asm volatile("ld.shared.v4.u32 {%0,%1,%2,%3}, [%4];"
                         : "=r"(x0), "=r"(x1), "=r"(x2), "=r"(x3) : "r"(RA + m * 2048));
            asm volatile("ld.shared.v4.u32 {%0,%1,%2,%3}, [%4];"
                         : "=r"(y0), "=r"(y1), "=r"(y2), "=r"(y3) : "r"(RA + m * 2048 + 1024));
            #pragma unroll
            for (int n = 0; n < 4; n++)
                mma_tf32(acc[m][n], x0, y0, x1, y1, bw[n][0], bw[n][1]);  // kb = 2p
            #pragma unroll
            for (int n = 0; n < 4; n++)
                mma_tf32(acc[m][n], x2, y2, x3, y3, bw[n][2], bw[n][3]);  // kb = 2p+1
        }
    }
}

// ------------------------------- step kernel --------------------------------
__global__ void __launch_bounds__(THREADS, 2) step_kernel(int t) {
    extern __shared__ char dsm[];
    uint32_t sb = smem_u32(dsm);
    sb = (sb + 127u) & ~127u;

    const int tid  = threadIdx.x;
    const int warp = tid >> 5, lane = tid & 31;
    const int wm = warp >> 2, wn = warp & 3;
    const int g  = lane >> 2, q = lane & 3;
    const int nhi   = blockIdx.y;
    const int nh    = nhi * 32;
    const int brow0 = blockIdx.x * 128;

    const float* __restrict__ hin  = g_h[t & 1];
    float*       __restrict__ hout = g_h[(t + 1) & 1];
    const float* __restrict__ xT   = g_xT + (size_t)t * BATCH * INFEAT;

    const uint32_t mb = sb + SMEM_CTRL;
    #define MB_FULL(S)  (mb + 8u * (S))
    #define MB_EMPTY(S) (mb + 24u + 8u * (S))

    if (tid == 0) {
        MBARRIER_INIT(MB_FULL(0), 256);  MBARRIER_INIT(MB_FULL(1), 256);
        MBARRIER_INIT(MB_FULL(2), 256);
        MBARRIER_INIT(MB_EMPTY(0), 8);   MBARRIER_INIT(MB_EMPTY(1), 8);
        MBARRIER_INIT(MB_EMPTY(2), 8);
    }
    __syncthreads();
    if (lane == 0) {        // pre-complete empty phase 0: stages free for gen 0
        MBAR_ARRIVE(MB_EMPTY(0)); MBAR_ARRIVE(MB_EMPTY(1)); MBAR_ARRIVE(MB_EMPTY(2));
    }

    // persistent cp.async addressing
    const int r0 = tid >> 3, cc0 = tid & 7;
    const uint32_t dstA = sb + r0 * 128 + (((uint32_t)cc0 ^ swz((uint32_t)(r0 & 7))) << 4);
    const uint32_t dstB = sb + 16384 + tid * 16;
    const float* srcA0  = hin + (size_t)(brow0 + r0) * HID + cc0 * 4;      // + C*32 + u*16384
    const float* srcAx0 = xT  + (size_t)(brow0 + r0) * INFEAT + cc0 * 4;   // + (C-16)*32 + u*3072
    const float* srcB0  = g_Wt + ((size_t)(nhi * NCHUNK) << 12) + tid * 4; // + C*4096 + u*1024

    #define LOAD_CHUNK(C) do {                                                        \
        if ((C) < 16) {                                                               \
            _Pragma("unroll") for (int u = 0; u < 4; u++)                             \
                cp16(dstA + ((C) % 3) * STAGE + u * 4096,                             \
                     srcA0 + (C) * 32 + (size_t)u * 16384);                           \
        } else {                                                                      \
            _Pragma("unroll") for (int u = 0; u < 4; u++)                             \
                cp16(dstA + ((C) % 3) * STAGE + u * 4096,                             \
                     srcAx0 + ((C) - 16) * 32 + (size_t)u * 3072);                    \
        }                                                                             \
        _Pragma("unroll") for (int u = 0; u < 4; u++)                                 \
            cp16(dstB + ((C) % 3) * STAGE + u * 4096, srcB0 + (C) * 4096 + u * 1024); \
        cp_arrive(MB_FULL((C) % 3));                                                  \
    } while (0)

    // prologue: chunks 0, 1 (stages fresh, no empty wait)
    LOAD_CHUNK(0);
    LOAD_CHUNK(1);

    float acc[4][4][4] = {};
    const uint32_t sg  = swz((uint32_t)g);
    const uint32_t RA0 = sb + (uint32_t)(wm * 64 + g) * 128 + (((uint32_t)q ^ sg) << 4);
    const uint32_t RA1 = sb + (uint32_t)(wm * 64 + g) * 128 + (((uint32_t)(4 + q) ^ sg) << 4);
    const uint32_t RB0 = sb + (uint32_t)(wn * 32 + g) * 128 + (((uint32_t)q ^ sg) << 4);
    const uint32_t RB1 = sb + (uint32_t)(wn * 32 + g) * 128 + (((uint32_t)(4 + q) ^ sg) << 4);

    #define STEP_ITER(KC) do {                                                        \
        if ((KC) + 2 < NCHUNK) {                                                      \
            MBARRIER_WAIT_PARITY(MB_EMPTY(((KC) + 2) % 3), ((((KC) + 2) / 3)) & 1);   \
            LOAD_CHUNK((KC) + 2);                                                     \
        }                                                                             \
        MBARRIER_WAIT_PARITY(MB_FULL((KC) % 3), ((KC) / 3) & 1);                      \
        mma_chunk<(KC) % 3>(acc, RA0, RA1, RB0, RB1);                                 \
        if (lane == 0) MBAR_ARRIVE(MB_EMPTY((KC) % 3));                               \
    } while (0)

    STEP_ITER(0);  STEP_ITER(1);  STEP_ITER(2);  STEP_ITER(3);  STEP_ITER(4);
    STEP_ITER(5);  STEP_ITER(6);  STEP_ITER(7);  STEP_ITER(8);  STEP_ITER(9);
    STEP_ITER(10); STEP_ITER(11); STEP_ITER(12); STEP_ITER(13); STEP_ITER(14);
    STEP_ITER(15); STEP_ITER(16); STEP_ITER(17); STEP_ITER(18);

    // -------------------- in-register LSTM epilogue -------------------------
    const int u0 = nh + wn * 8 + 2 * q;
    const float2 bi = *(const float2*)(g_bias + 0 * HID + u0);
    const float2 bf = *(const float2*)(g_bias + 1 * HID + u0);
    const float2 bg = *(const float2*)(g_bias + 2 * HID + u0);
    const float2 bo = *(const float2*)(g_bias + 3 * HID + u0);

    #pragma unroll
    for (int m = 0; m < 4; m++) {
        #pragma unroll
        for (int rh = 0; rh < 2; rh++) {
            const int row = brow0 + wm * 64 + m * 16 + g + rh * 8;
            const int s0 = rh * 2;
            float* cptr = g_c  + (size_t)row * HID + u0;
            float* hptr = hout + (size_t)row * HID + u0;
            float2 cv = *(const float2*)(cptr);

            float i0 = sigm (acc[m][0][s0]     + bi.x);
            float f0 = sigm (acc[m][1][s0]     + bf.x);
            float g0 = tanh_(acc[m][2][s0]     + bg.x);
            float o0 = sigm (acc[m][3][s0]     + bo.x);
            float i1 = sigm (acc[m][0][s0 + 1] + bi.y);
            float f1 = sigm (acc[m][1][s0 + 1] + bf.y);
            float g1 = tanh_(acc[m][2][s0 + 1] + bg.y);
            float o1 = sigm (acc[m][3][s0 + 1] + bo.y);

            float cn0 = fmaf(f0, cv.x, i0 * g0);
            float cn1 = fmaf(f1, cv.y, i1 * g1);
            *(float2*)(cptr) = make_float2(cn0, cn1);
            *(float2*)(hptr) = make_float2(to_tf32(o0 * tanh_(cn0)),
                                           to_tf32(o1 * tanh_(cn1)));
        }
    }
}

// ------------------------------- final kernel -------------------------------
__global__ void final_kernel(const float* __restrict__ Wout, const float* __restrict__ bout,
                             float* __restrict__ out) {
    int idx = blockIdx.x * blockDim.x + threadIdx.x;
    if (idx >= BATCH * 10) return;
    int b = idx / 10, cls = idx % 10;
    const float* h  = g_h[0] + (size_t)b * HID;        // step 31 wrote g_h[0]
    const float* wv = Wout + (size_t)cls * HID;
    float acc = 0.f;
    #pragma unroll 4
    for (int i = 0; i < HID; i += 4) {
        float4 hv = *(const float4*)(h + i);
        float4 wf = *(const float4*)(wv + i);
        acc = fmaf(hv.x, wf.x, acc);
        acc = fmaf(hv.y, wf.y, acc);
        acc = fmaf(hv.z, wf.z, acc);
        acc = fmaf(hv.w, wf.w, acc);
    }
    out[idx] = acc + bout[cls];
}

// --------------------------------- launch -----------------------------------
extern "C" void kernel_launch(void* const* d_in, const int* in_sizes, int n_in,
                              void* d_out, int out_size) {
    const float* inputs = (const float*)d_in[0];
    const float* h0     = (const float*)d_in[1];
    const float* c0     = (const float*)d_in[2];
    const float* W_ih   = (const float*)d_in[3];
    const float* W_hh   = (const float*)d_in[4];
    const float* b_ih   = (const float*)d_in[5];
    const float* b_hh   = (const float*)d_in[6];
    const float* W_out  = (const float*)d_in[7];
    const float* b_out  = (const float*)d_in[8];
    float* out = (float*)d_out;
    (void)in_sizes; (void)n_in; (void)out_size;

    cudaFuncSetAttribute(step_kernel, cudaFuncAttributeMaxDynamicSharedMemorySize, SMEM_ALLOC);

    prep_x_kernel<<<(BATCH * 3 * 32 * 32 + 255) / 256, 256>>>(inputs);
    prep_misc_kernel<<<(BATCH * HID + 255) / 256, 256>>>(h0, c0, b_ih, b_hh);
    prep_w_kernel<<<(WT_FLOATS + 255) / 256, 256>>>(W_ih, W_hh);

    dim3 grid(BATCH / 128, HID / 32);   // (64, 16) = 1024 CTAs
    for (int t = 0; t < TSTEPS; t++)
        step_kernel<<<grid, THREADS, SMEM_ALLOC>>>(t);

    final_kernel<<<(BATCH * 10 + 255) / 256, 256>>>(W_out, b_out, out);
}

// round 17
// speedup vs baseline: 1.0172x; 1.0172x over previous
#include <cuda_runtime.h>
#include <cstdint>
#include <cstddef>

// ============================================================================
// LSTM (B=8192, H=512, T=32, F=96) on sm_100 via mma.sync.m16n8k8 TF32.
//
// R15/R16/R17 = R13 (best: 3862us; R14's mbarrier flow control was NEUTRAL
// -> reverted to bar.sync) + c-tile smem prefetch: the 128x32 c slice is
// cp.async'd into a dedicated 16KB buffer (same row/XOR-swizzle image as
// A-chunks) at kernel start, in its own commit group, and read in the
// epilogue via conflict-free ld.shared.v2 instead of 8 dependent ~600cyc
// LDGs issued when the CTA has nothing left to overlap them with.
// Smem 96.25 -> 112.5 KB/CTA; still 2 CTAs/SM. Math bit-identical.
// ============================================================================

#define DEVI __device__ __forceinline__

#define BATCH   8192
#define HID     512
#define G4      2048
#define TSTEPS  32
#define INFEAT  96
#define NCHUNK  19
#define THREADS 256

#define STAGE     32768              // A 16KB | B 16KB
#define CBUF_OFF  (3 * STAGE)        // 98304: 16KB c-tile buffer
#define SMEM_NEED (CBUF_OFF + 16384)
#define SMEM_ALLOC (SMEM_NEED + 256)

#define WT_FLOATS (16 * NCHUNK * 128 * 32)   // 4.75MB pre-tiled W

// ------------------------- device scratch (no allocs) -----------------------
__device__ float g_h[2][BATCH * HID];
__device__ float g_c[BATCH * HID];
__device__ float g_bias[G4];
__device__ float g_Wt[WT_FLOATS];
__device__ float g_xT[TSTEPS * BATCH * INFEAT];

// ------------------------------ helpers -------------------------------------
DEVI uint32_t smem_u32(const void* p) {
    uint32_t a;
    asm("{ .reg .u64 t; cvta.to.shared.u64 t, %1; cvt.u32.u64 %0, t; }" : "=r"(a) : "l"(p));
    return a;
}
DEVI float to_tf32(float x) {
    uint32_t o;
    asm("cvt.rna.tf32.f32 %0, %1;" : "=r"(o) : "f"(x));
    return __uint_as_float(o);
}
DEVI float ex2f(float x) { float y; asm("ex2.approx.f32 %0, %1;" : "=f"(y) : "f"(x)); return y; }
DEVI float rcpf(float x) { float y; asm("rcp.approx.f32 %0, %1;" : "=f"(y) : "f"(x)); return y; }
DEVI float sigm(float x) { return rcpf(1.0f + ex2f(x * -1.44269504088896f)); }
DEVI float tanh_(float x) { return fmaf(2.0f, sigm(x + x), -1.0f); }

DEVI uint32_t swz(uint32_t g) { return ((g & 1u) << 2) | (g >> 1); }

DEVI void cp16(uint32_t sdst, const void* gsrc) {
    asm volatile("cp.async.cg.shared.global [%0], [%1], 16;" :: "r"(sdst), "l"(gsrc) : "memory");
}
DEVI void mma_tf32(float* c, uint32_t a0, uint32_t a1, uint32_t a2, uint32_t a3,
                   uint32_t b0, uint32_t b1) {
    asm volatile(
        "mma.sync.aligned.m16n8k8.row.col.f32.tf32.tf32.f32 "
        "{%0,%1,%2,%3}, {%4,%5,%6,%7}, {%8,%9}, {%0,%1,%2,%3};"
        : "+f"(c[0]), "+f"(c[1]), "+f"(c[2]), "+f"(c[3])
        : "r"(a0), "r"(a1), "r"(a2), "r"(a3), "r"(b0), "r"(b1));
}

// ------------------------------ prep kernels --------------------------------
__global__ void prep_x_kernel(const float* __restrict__ in) {
    int idx = blockIdx.x * blockDim.x + threadIdx.x;
    if (idx >= BATCH * 3 * 32 * 32) return;
    int w  = idx & 31;
    int t  = (idx >> 5) & 31;
    int c3 = idx >> 10;
    int ch = c3 % 3;
    int b  = c3 / 3;
    g_xT[((size_t)t * BATCH + b) * INFEAT + w * 3 + ch] = to_tf32(in[idx]);
}

__global__ void prep_misc_kernel(const float* __restrict__ h0, const float* __restrict__ c0,
                                 const float* __restrict__ bih, const float* __restrict__ bhh) {
    int i = blockIdx.x * blockDim.x + threadIdx.x;
    if (i < BATCH * HID) {
        g_h[0][i] = to_tf32(h0[i]);
        g_c[i]    = c0[i];
    }
    if (i < G4) g_bias[i] = bih[i] + bhh[i];
}

// g_Wt[(nhi*NCHUNK + kc)*4096 + r*32 + c]: row r = gate(r)*512 + nhi*32 +
// unit(r), swizzle (chunk ^= swz(r&7)) baked in.
__global__ void prep_w_kernel(const float* __restrict__ Wih, const float* __restrict__ Whh) {
    int idx = blockIdx.x * blockDim.x + threadIdx.x;
    if (idx >= WT_FLOATS) return;
    int pos = idx & 4095;
    int kc  = (idx >> 12) % NCHUNK;
    int nhi = idx / (NCHUNK * 4096);
    int r   = pos >> 5;
    int c   = pos & 31;
    int cc_dst = c >> 2, j = c & 3;
    int cc_src = cc_dst ^ (int)swz((uint32_t)(r & 7));
    int k_local = cc_src * 4 + j;
    int wrow = ((r >> 3) & 3) * HID + nhi * 32 + ((r >> 5) << 3) + (r & 7);
    float v;
    if (kc < 16) v = Whh[(size_t)wrow * HID    + kc * 32        + k_local];
    else         v = Wih[(size_t)wrow * INFEAT + (kc - 16) * 32 + k_local];
    g_Wt[idx] = to_tf32(v);
}

// --------------------- templated loader / compute bodies --------------------
template<int S, int AP>
DEVI void load_stage(uint32_t dstA, uint32_t dstB,
                     const float* __restrict__ srcA, const float* __restrict__ srcB) {
    #pragma unroll
    for (int u = 0; u < 4; u++)
        cp16(dstA + S * STAGE + u * 4096, srcA + (size_t)u * AP);
    #pragma unroll
    for (int u = 0; u < 4; u++)
        cp16(dstB + S * STAGE + u * 4096, srcB + u * 1024);
    asm volatile("cp.async.commit_group;" ::: "memory");
}

template<int S>
DEVI void mma_chunk(float (&acc)[4][4][4],
                    uint32_t RA0, uint32_t RA1, uint32_t RB0, uint32_t RB1) {
    #pragma unroll
    for (int p = 0; p < 2; p++) {
        const uint32_t RA = (p ? RA1 : RA0) + S * STAGE;
        const uint32_t RB = (p ? RB1 : RB0) + S * STAGE + 16384;
        uint32_t bw[4][4];
        #pragma unroll
        for (int n = 0; n < 4; n++)
            asm volatile("ld.shared.v4.u32 {%0,%1,%2,%3}, [%4];"
                         : "=r"(bw[n][0]), "=r"(bw[n][1]), "=r"(bw[n][2]), "=r"(bw[n][3])
                         : "r"(RB + n * 1024));
        #pragma unroll
        for (int m = 0; m < 4; m++) {
            uint32_t x0, x1, x2, x3, y0, y1, y2, y3;
            asm volatile("ld.shared.v4.u32 {%0,%1,%2,%3}, [%4];"
                         : "=r"(x0), "=r"(x1), "=r"(x2), "=r"(x3) : "r"(RA + m * 2048));
            asm volatile("ld.shared.v4.u32 {%0,%1,%2,%3}, [%4];"
                         : "=r"(y0), "=r"(y1), "=r"(y2), "=r"(y3) : "r"(RA + m * 2048 + 1024));
            #pragma unroll
            for (int n = 0; n < 4; n++)
                mma_tf32(acc[m][n], x0, y0, x1, y1, bw[n][0], bw[n][1]);  // kb = 2p
            #pragma unroll
            for (int n = 0; n < 4; n++)
                mma_tf32(acc[m][n], x2, y2, x3, y3, bw[n][2], bw[n][3]);  // kb = 2p+1
        }
    }
}

#define WAITG(N) asm volatile("cp.async.wait_group " #N ";" ::: "memory")

// ------------------------------- step kernel --------------------------------
__global__ void __launch_bounds__(THREADS, 2) step_kernel(int t) {
    extern __shared__ char dsm[];
    uint32_t sb = smem_u32(dsm);
    sb = (sb + 127u) & ~127u;

    const int tid  = threadIdx.x;
    const int warp = tid >> 5, lane = tid & 31;
    const int wm = warp >> 2, wn = warp & 3;
    const int g  = lane >> 2, q = lane & 3;
    const int nhi   = blockIdx.y;
    const int nh    = nhi * 32;
    const int brow0 = blockIdx.x * 128;

    const float* __restrict__ hin  = g_h[t & 1];
    float*       __restrict__ hout = g_h[(t + 1) & 1];
    const float* __restrict__ xT   = g_xT + (size_t)t * BATCH * INFEAT;

    // persistent cp.async addressing
    const int r0 = tid >> 3, cc0 = tid & 7;
    const uint32_t dstA = sb + r0 * 128 + (((uint32_t)cc0 ^ swz((uint32_t)(r0 & 7))) << 4);
    const uint32_t dstB = sb + 16384 + tid * 16;
    const float* srcA  = hin + (size_t)(brow0 + r0) * HID + cc0 * 4;
    const float* srcB  = g_Wt + ((size_t)(nhi * NCHUNK) << 12) + tid * 4;
    const float* srcAx = xT + (size_t)(brow0 + r0) * INFEAT + cc0 * 4;

    // c-tile prefetch: 128 rows x 32 cols (nh..nh+31) into CBUF with the
    // same row/swizzle image as A chunks. Own commit group (drains early).
    {
        const float* srcC = g_c + (size_t)(brow0 + r0) * HID + nh + cc0 * 4;
        #pragma unroll
        for (int u = 0; u < 4; u++)
            cp16(dstA + CBUF_OFF + u * 4096, srcC + (size_t)u * 32 * HID);
        asm volatile("cp.async.commit_group;" ::: "memory");
    }

    // persistent fragment base registers (k-permutation chunk (4p+q)^swz(g))
    const uint32_t sg  = swz((uint32_t)g);
    const uint32_t RA0 = sb + (uint32_t)(wm * 64 + g) * 128 + (((uint32_t)q ^ sg) << 4);
    const uint32_t RA1 = sb + (uint32_t)(wm * 64 + g) * 128 + (((uint32_t)(4 + q) ^ sg) << 4);
    const uint32_t RB0 = sb + (uint32_t)(wn * 32 + g) * 128 + (((uint32_t)q ^ sg) << 4);
    const uint32_t RB1 = sb + (uint32_t)(wn * 32 + g) * 128 + (((uint32_t)(4 + q) ^ sg) << 4);

    // prologue: chunks 0, 1
    load_stage<0, 16384>(dstA, dstB, srcA,      srcB);
    load_stage<1, 16384>(dstA, dstB, srcA + 32, srcB + 4096);
    srcA += 64; srcB += 8192;

    float acc[4][4][4] = {};

    // kc = 0..11 (4 groups of 3; loads cover chunks 2..13, all h)
    for (int i = 0; i < 4; i++) {
        WAITG(1); __syncthreads();
        load_stage<2, 16384>(dstA, dstB, srcA, srcB); srcA += 32; srcB += 4096;
        mma_chunk<0>(acc, RA0, RA1, RB0, RB1);

        WAITG(1); __syncthreads();
        load_stage<0, 16384>(dstA, dstB, srcA, srcB); srcA += 32; srcB += 4096;
        mma_chunk<1>(acc, RA0, RA1, RB0, RB1);

        WAITG(1); __syncthreads();
        load_stage<1, 16384>(dstA, dstB, srcA, srcB); srcA += 32; srcB += 4096;
        mma_chunk<2>(acc, RA0, RA1, RB0, RB1);
    }

    // kc = 12 (load chunk 14, h)
    WAITG(1); __syncthreads();
    load_stage<2, 16384>(dstA, dstB, srcA, srcB); srcA += 32; srcB += 4096;
    mma_chunk<0>(acc, RA0, RA1, RB0, RB1);
    // kc = 13 (load chunk 15, h)
    WAITG(1); __syncthreads();
    load_stage<0, 16384>(dstA, dstB, srcA, srcB); srcB += 4096;
    mma_chunk<1>(acc, RA0, RA1, RB0, RB1);
    // kc = 14 (load chunk 16, x)
    WAITG(1); __syncthreads();
    load_stage<1, 3072>(dstA, dstB, srcAx, srcB); srcB += 4096;
    mma_chunk<2>(acc, RA0, RA1, RB0, RB1);
    // kc = 15 (load chunk 17, x)
    WAITG(1); __syncthreads();
    load_stage<2, 3072>(dstA, dstB, srcAx + 32, srcB); srcB += 4096;
    mma_chunk<0>(acc, RA0, RA1, RB0, RB1);
    // kc = 16 (load chunk 18, x)
    WAITG(1); __syncthreads();
    load_stage<0, 3072>(dstA, dstB, srcAx + 64, srcB);
    mma_chunk<1>(acc, RA0, RA1, RB0, RB1);
    // kc = 17
    WAITG(1); __syncthreads();
    mma_chunk<2>(acc, RA0, RA1, RB0, RB1);
    // kc = 18
    WAITG(0); __syncthreads();
    mma_chunk<0>(acc, RA0, RA1, RB0, RB1);

    // -------------------- in-register LSTM epilogue -------------------------
    const int u0 = nh + wn * 8 + 2 * q;
    const float2 bi = *(const float2*)(g_bias + 0 * HID + u0);
    const float2 bf = *(const float2*)(g_bias + 1 * HID + u0);
    const float2 bg = *(const float2*)(g_bias + 2 * HID + u0);
    const float2 bo = *(const float2*)(g_bias + 3 * HID + u0);

    // c fragment base in CBUF: row wm*64+g (+m*16+rh*8), chunk (2wn+(q>>1))^sg,
    // half (q&1)*8 -- conflict-free v2 reads.
    const uint32_t cfb = sb + CBUF_OFF + (uint32_t)(wm * 64 + g) * 128
                       + (((uint32_t)(2 * wn + (q >> 1)) ^ sg) << 4) + ((uint32_t)(q & 1) << 3);

    #pragma unroll
    for (int m = 0; m < 4; m++) {
        #pragma unroll
        for (int rh = 0; rh < 2; rh++) {
            const int row = brow0 + wm * 64 + m * 16 + g + rh * 8;
            const int s0 = rh * 2;
            float* cptr = g_c  + (size_t)row * HID + u0;
            float* hptr = hout + (size_t)row * HID + u0;
            float2 cv;
            asm volatile("ld.shared.v2.f32 {%0,%1}, [%2];"
                         : "=f"(cv.x), "=f"(cv.y)
                         : "r"(cfb + (uint32_t)(m * 16 + rh * 8) * 128));

            float i0 = sigm (acc[m][0][s0]     + bi.x);
            float f0 = sigm (acc[m][1][s0]     + bf.x);
            float g0 = tanh_(acc[m][2][s0]     + bg.x);
            float o0 = sigm (acc[m][3][s0]     + bo.x);
            float i1 = sigm (acc[m][0][s0 + 1] + bi.y);
            float f1 = sigm (acc[m][1][s0 + 1] + bf.y);
            float g1 = tanh_(acc[m][2][s0 + 1] + bg.y);
            float o1 = sigm (acc[m][3][s0 + 1] + bo.y);

            float cn0 = fmaf(f0, cv.x, i0 * g0);
            float cn1 = fmaf(f1, cv.y, i1 * g1);
            *(float2*)(cptr) = make_float2(cn0, cn1);
            *(float2*)(hptr) = make_float2(to_tf32(o0 * tanh_(cn0)),
                                           to_tf32(o1 * tanh_(cn1)));
        }
    }
}

// ------------------------------- final kernel -------------------------------
__global__ void final_kernel(const float* __restrict__ Wout, const float* __restrict__ bout,
                             float* __restrict__ out) {
    int idx = blockIdx.x * blockDim.x + threadIdx.x;
    if (idx >= BATCH * 10) return;
    int b = idx / 10, cls = idx % 10;
    const float* h  = g_h[0] + (size_t)b * HID;        // step 31 wrote g_h[0]
    const float* wv = Wout + (size_t)cls * HID;
    float acc = 0.f;
    #pragma unroll 4
    for (int i = 0; i < HID; i += 4) {
        float4 hv = *(const float4*)(h + i);
        float4 wf = *(const float4*)(wv + i);
        acc = fmaf(hv.x, wf.x, acc);
        acc = fmaf(hv.y, wf.y, acc);
        acc = fmaf(hv.z, wf.z, acc);
        acc = fmaf(hv.w, wf.w, acc);
    }
    out[idx] = acc + bout[cls];
}

// --------------------------------- launch -----------------------------------
extern "C" void kernel_launch(void* const* d_in, const int* in_sizes, int n_in,
                              void* d_out, int out_size) {
    const float* inputs = (const float*)d_in[0];
    const float* h0     = (const float*)d_in[1];
    const float* c0     = (const float*)d_in[2];
    const float* W_ih   = (const float*)d_in[3];
    const float* W_hh   = (const float*)d_in[4];
    const float* b_ih   = (const float*)d_in[5];
    const float* b_hh   = (const float*)d_in[6];
    const float* W_out  = (const float*)d_in[7];
    const float* b_out  = (const float*)d_in[8];
    float* out = (float*)d_out;
    (void)in_sizes; (void)n_in; (void)out_size;

    cudaFuncSetAttribute(step_kernel, cudaFuncAttributeMaxDynamicSharedMemorySize, SMEM_ALLOC);

    prep_x_kernel<<<(BATCH * 3 * 32 * 32 + 255) / 256, 256>>>(inputs);
    prep_misc_kernel<<<(BATCH * HID + 255) / 256, 256>>>(h0, c0, b_ih, b_hh);
    prep_w_kernel<<<(WT_FLOATS + 255) / 256, 256>>>(W_ih, W_hh);

    dim3 grid(BATCH / 128, HID / 32);   // (64, 16) = 1024 CTAs
    for (int t = 0; t < TSTEPS; t++)
        step_kernel<<<grid, THREADS, SMEM_ALLOC>>>(t);

    final_kernel<<<(BATCH * 10 + 255) / 256, 256>>>(W_out, b_out, out);
}